// round 5
// baseline (speedup 1.0000x reference)
#include <cuda_runtime.h>
#include <cuda_bf16.h>
#include <cstdint>

// Problem dims (fixed by dataset): M = 8*4096 rows, D=1024, H=4096
#define M_ROWS 32768
#define D_IN   1024
#define H_MID  4096
#define W_NUMEL (4096*1024)

// ---------------- scratch (__device__ globals; allocation-free rule) -------
__device__ __align__(1024) __nv_bfloat16 g_A1[(size_t)M_ROWS * D_IN];
__device__ __align__(1024) __nv_bfloat16 g_A2[(size_t)M_ROWS * H_MID];
__device__ __align__(1024) float         g_H1[(size_t)M_ROWS * H_MID];
__device__ __align__(1024) __nv_bfloat16 g_W1[(size_t)W_NUMEL];
__device__ __align__(1024) __nv_bfloat16 g_W2[(size_t)W_NUMEL];
__device__ float g_rowdq1[M_ROWS];
__device__ float g_rowdq2[M_ROWS];
__device__ float g_part[1024];
__device__ float g_ws1[2];   // [quant scale, dequant factor]
__device__ float g_ws2[2];

// ---------------- small helpers --------------------------------------------
__device__ __forceinline__ float block_sum(float v, float* sb) {
    int tid = threadIdx.x;
    #pragma unroll
    for (int o = 16; o; o >>= 1) v += __shfl_xor_sync(0xffffffffu, v, o);
    __syncthreads();
    if ((tid & 31) == 0) sb[tid >> 5] = v;
    __syncthreads();
    int nw = blockDim.x >> 5;
    float t = (tid < nw) ? sb[tid] : 0.f;
    #pragma unroll
    for (int o = 16; o; o >>= 1) t += __shfl_xor_sync(0xffffffffu, t, o);
    if (tid == 0) sb[0] = t;
    __syncthreads();
    return sb[0];
}

__device__ __forceinline__ float block_max(float v, float* sb) {
    int tid = threadIdx.x;
    #pragma unroll
    for (int o = 16; o; o >>= 1) v = fmaxf(v, __shfl_xor_sync(0xffffffffu, v, o));
    __syncthreads();
    if ((tid & 31) == 0) sb[tid >> 5] = v;
    __syncthreads();
    int nw = blockDim.x >> 5;
    float t = (tid < nw) ? sb[tid] : 0.f;
    #pragma unroll
    for (int o = 16; o; o >>= 1) t = fmaxf(t, __shfl_xor_sync(0xffffffffu, t, o));
    if (tid == 0) sb[0] = t;
    __syncthreads();
    return sb[0];
}

// ---------------- weight quantization (deterministic) -----------------------
__global__ void __launch_bounds__(256) wabs_partial_kernel(
    const float* __restrict__ w, float* __restrict__ part)
{
    __shared__ float sb[64];
    int tid = threadIdx.x;
    const float4* p = (const float4*)w + (size_t)blockIdx.x * 1024;
    float s = 0.f;
    #pragma unroll
    for (int i = 0; i < 4; i++) {
        float4 v = p[tid + 256 * i];
        s += fabsf(v.x) + fabsf(v.y) + fabsf(v.z) + fabsf(v.w);
    }
    s = block_sum(s, sb);
    if (tid == 0) part[blockIdx.x] = s;
}

__global__ void __launch_bounds__(1024) wfinal_kernel(
    const float* __restrict__ part, float* __restrict__ wsout, float n)
{
    __shared__ float sb[64];
    float s = part[threadIdx.x];
    s = block_sum(s, sb);
    if (threadIdx.x == 0) {
        float mean = fmaxf(s / n, 1e-5f);
        wsout[0] = 1.0f / mean;  // quant multiplier
        wsout[1] = mean;         // dequant factor
    }
}

__global__ void __launch_bounds__(256) wquant_kernel(
    const float* __restrict__ w, const float* __restrict__ ws,
    __nv_bfloat16* __restrict__ q)
{
    float s = ws[0];
    size_t base = ((size_t)blockIdx.x * 256 + threadIdx.x) * 8;
    float4 a = *(const float4*)(w + base);
    float4 b = *(const float4*)(w + base + 4);
    __nv_bfloat16 o[8];
    o[0] = __float2bfloat16(fminf(fmaxf(rintf(a.x * s), -1.f), 1.f));
    o[1] = __float2bfloat16(fminf(fmaxf(rintf(a.y * s), -1.f), 1.f));
    o[2] = __float2bfloat16(fminf(fmaxf(rintf(a.z * s), -1.f), 1.f));
    o[3] = __float2bfloat16(fminf(fmaxf(rintf(a.w * s), -1.f), 1.f));
    o[4] = __float2bfloat16(fminf(fmaxf(rintf(b.x * s), -1.f), 1.f));
    o[5] = __float2bfloat16(fminf(fmaxf(rintf(b.y * s), -1.f), 1.f));
    o[6] = __float2bfloat16(fminf(fmaxf(rintf(b.z * s), -1.f), 1.f));
    o[7] = __float2bfloat16(fminf(fmaxf(rintf(b.w * s), -1.f), 1.f));
    *(uint4*)(q + base) = *(uint4*)o;
}

// ---------------- fused LayerNorm + per-row int8 fake-quant -----------------
// One block (256 threads) per row; NV float4 per thread (NV = L/1024).
template <int NV>
__global__ void __launch_bounds__(256) ln_quant_kernel(
    const float* __restrict__ x, const float* __restrict__ g,
    const float* __restrict__ b, __nv_bfloat16* __restrict__ q,
    float* __restrict__ rowdq)
{
    constexpr int L = NV * 1024;
    __shared__ float sb[64];
    int row = blockIdx.x, tid = threadIdx.x;
    const float4* xr = (const float4*)(x + (size_t)row * L);
    float4 v[NV];
    float s = 0.f;
    #pragma unroll
    for (int i = 0; i < NV; i++) {
        v[i] = xr[tid + 256 * i];
        s += v[i].x + v[i].y + v[i].z + v[i].w;
    }
    float mu = block_sum(s, sb) * (1.0f / L);
    float s2 = 0.f;
    #pragma unroll
    for (int i = 0; i < NV; i++) {
        float dx = v[i].x - mu, dy = v[i].y - mu, dz = v[i].z - mu, dw = v[i].w - mu;
        s2 += dx * dx + dy * dy + dz * dz + dw * dw;
    }
    float rstd = rsqrtf(block_sum(s2, sb) * (1.0f / L) + 1e-5f);

    const float4* g4 = (const float4*)g;
    const float4* b4 = (const float4*)b;
    float y[NV * 4];
    float amax = 0.f;
    #pragma unroll
    for (int i = 0; i < NV; i++) {
        float4 gv = g4[tid + 256 * i];
        float4 bv = b4[tid + 256 * i];
        y[i * 4 + 0] = (v[i].x - mu) * rstd * gv.x + bv.x;
        y[i * 4 + 1] = (v[i].y - mu) * rstd * gv.y + bv.y;
        y[i * 4 + 2] = (v[i].z - mu) * rstd * gv.z + bv.z;
        y[i * 4 + 3] = (v[i].w - mu) * rstd * gv.w + bv.w;
        #pragma unroll
        for (int j = 0; j < 4; j++) amax = fmaxf(amax, fabsf(y[i * 4 + j]));
    }
    amax = block_max(amax, sb);
    float scale = 127.f / fmaxf(amax, 1e-5f);
    if (tid == 0) rowdq[row] = 1.0f / scale;

    __nv_bfloat16* qr = q + (size_t)row * L;
    #pragma unroll
    for (int i = 0; i < NV; i++) {
        __nv_bfloat16 o[4];
        #pragma unroll
        for (int j = 0; j < 4; j++) {
            float qv = fminf(fmaxf(rintf(y[i * 4 + j] * scale), -128.f), 127.f);
            o[j] = __float2bfloat16(qv);
        }
        *(uint2*)(qr + (size_t)(tid + 256 * i) * 4) = *(uint2*)o;
    }
}

// ---------------- bf16 GEMM (mma.sync m16n8k16), fused dequant epilogue -----
__device__ __forceinline__ void mma16816(float* c, const uint32_t* a, const uint32_t* b) {
    asm volatile(
        "mma.sync.aligned.m16n8k16.row.col.f32.bf16.bf16.f32 "
        "{%0,%1,%2,%3}, {%4,%5,%6,%7}, {%8,%9}, {%0,%1,%2,%3};\n"
        : "+f"(c[0]), "+f"(c[1]), "+f"(c[2]), "+f"(c[3])
        : "r"(a[0]), "r"(a[1]), "r"(a[2]), "r"(a[3]), "r"(b[0]), "r"(b[1]));
}
__device__ __forceinline__ void ldsm4(uint32_t* r, uint32_t addr) {
    asm volatile("ldmatrix.sync.aligned.m8n8.x4.shared.b16 {%0,%1,%2,%3}, [%4];\n"
        : "=r"(r[0]), "=r"(r[1]), "=r"(r[2]), "=r"(r[3]) : "r"(addr));
}
__device__ __forceinline__ void ldsm2(uint32_t* r, uint32_t addr) {
    asm volatile("ldmatrix.sync.aligned.m8n8.x2.shared.b16 {%0,%1}, [%2];\n"
        : "=r"(r[0]), "=r"(r[1]) : "r"(addr));
}
__device__ __forceinline__ void cp_async16(uint32_t dst, const void* src) {
    asm volatile("cp.async.cg.shared.global [%0], [%1], 16;\n" :: "r"(dst), "l"(src) : "memory");
}

// smem tile: 128 rows x 32 bf16, padded row stride 40 halves (80 bytes)
#define TILE_B (128 * 40 * 2)

__device__ __forceinline__ void load_tiles(
    const __nv_bfloat16* A, const __nv_bfloat16* B,
    uint32_t sA, uint32_t sB, int m0, int n0, int k0, int K, int tid)
{
    #pragma unroll
    for (int i = 0; i < 2; i++) {
        int c = tid + 256 * i;
        int row = c >> 2;
        int kc = (c & 3) * 8;                 // halves
        cp_async16(sA + row * 80 + kc * 2, A + (size_t)(m0 + row) * K + k0 + kc);
        cp_async16(sB + row * 80 + kc * 2, B + (size_t)(n0 + row) * K + k0 + kc);
    }
}

__global__ void __launch_bounds__(256) gemm_bitlinear_kernel(
    const __nv_bfloat16* __restrict__ A,   // [M, K] bf16 (int values)
    const __nv_bfloat16* __restrict__ B,   // [N, K] bf16 (ternary)
    const float* __restrict__ rowdq,       // [M]
    const float* __restrict__ ws,          // ws[1] = weight dequant
    const float* __restrict__ bias,        // [N]
    float* __restrict__ out,               // [M, N]
    int N, int K, int do_gelu)
{
    __shared__ __align__(16) unsigned char smem[2 * 2 * TILE_B];
    uint32_t sbase = (uint32_t)__cvta_generic_to_shared(smem);
    int tid = threadIdx.x;
    int m0 = blockIdx.y * 128, n0 = blockIdx.x * 128;
    int lane = tid & 31, wid = tid >> 5;
    int wm = (wid >> 2) * 64, wn = (wid & 3) * 32;

    float acc[4][4][4];
    #pragma unroll
    for (int i = 0; i < 4; i++)
        #pragma unroll
        for (int j = 0; j < 4; j++)
            #pragma unroll
            for (int l = 0; l < 4; l++) acc[i][j][l] = 0.f;

    int nk = K >> 5;
    load_tiles(A, B, sbase, sbase + TILE_B, m0, n0, 0, K, tid);
    asm volatile("cp.async.commit_group;\n");
    int buf = 0;
    for (int kt = 0; kt < nk; kt++) {
        asm volatile("cp.async.wait_group 0;\n" ::: "memory");
        __syncthreads();
        if (kt + 1 < nk) {
            uint32_t off = (uint32_t)(buf ^ 1) * (2 * TILE_B);
            load_tiles(A, B, sbase + off, sbase + off + TILE_B, m0, n0, (kt + 1) << 5, K, tid);
            asm volatile("cp.async.commit_group;\n");
        }
        uint32_t aBase = sbase + (uint32_t)buf * (2 * TILE_B);
        uint32_t bBase = aBase + TILE_B;
        #pragma unroll
        for (int kk = 0; kk < 2; kk++) {
            uint32_t a[4][4], b[4][2];
            #pragma unroll
            for (int mi = 0; mi < 4; mi++) {
                uint32_t addr = aBase + (uint32_t)(wm + mi * 16 + (lane & 15)) * 80
                              + (uint32_t)(kk * 16 + (lane >> 4) * 8) * 2;
                ldsm4(a[mi], addr);
            }
            #pragma unroll
            for (int ni = 0; ni < 4; ni++) {
                int l = lane & 15;
                uint32_t addr = bBase + (uint32_t)(wn + ni * 8 + (l & 7)) * 80
                              + (uint32_t)(kk * 16 + (l >> 3) * 8) * 2;
                ldsm2(b[ni], addr);
            }
            #pragma unroll
            for (int mi = 0; mi < 4; mi++)
                #pragma unroll
                for (int ni = 0; ni < 4; ni++)
                    mma16816(acc[mi][ni], a[mi], b[ni]);
        }
        buf ^= 1;
    }

    // Epilogue: dequant + bias (+ exact-erf GELU)
    float wv = ws[1];
    #pragma unroll
    for (int mi = 0; mi < 4; mi++) {
        int r0 = m0 + wm + mi * 16 + (lane >> 2);
        float dq0 = rowdq[r0] * wv;
        float dq1 = rowdq[r0 + 8] * wv;
        #pragma unroll
        for (int ni = 0; ni < 4; ni++) {
            int col = n0 + wn + ni * 8 + (lane & 3) * 2;
            float bs0 = bias[col], bs1 = bias[col + 1];
            float v0 = acc[mi][ni][0] * dq0 + bs0;
            float v1 = acc[mi][ni][1] * dq0 + bs1;
            float v2 = acc[mi][ni][2] * dq1 + bs0;
            float v3 = acc[mi][ni][3] * dq1 + bs1;
            if (do_gelu) {
                v0 = 0.5f * v0 * (1.f + erff(v0 * 0.70710678118654752f));
                v1 = 0.5f * v1 * (1.f + erff(v1 * 0.70710678118654752f));
                v2 = 0.5f * v2 * (1.f + erff(v2 * 0.70710678118654752f));
                v3 = 0.5f * v3 * (1.f + erff(v3 * 0.70710678118654752f));
            }
            *(float2*)&out[(size_t)r0 * N + col]       = make_float2(v0, v1);
            *(float2*)&out[(size_t)(r0 + 8) * N + col] = make_float2(v2, v3);
        }
    }
}

// ---------------- launch ----------------------------------------------------
extern "C" void kernel_launch(void* const* d_in, const int* in_sizes, int n_in,
                              void* d_out, int out_size)
{
    const float* x    = (const float*)d_in[0];
    const float* ln1g = (const float*)d_in[1];
    const float* ln1b = (const float*)d_in[2];
    const float* w1   = (const float*)d_in[3];
    const float* b1   = (const float*)d_in[4];
    const float* ln2g = (const float*)d_in[5];
    const float* ln2b = (const float*)d_in[6];
    const float* w2   = (const float*)d_in[7];
    const float* b2   = (const float*)d_in[8];
    float* out = (float*)d_out;

    void *pA1, *pA2, *pH1, *pW1, *pW2, *pdq1, *pdq2, *ppart, *pws1, *pws2;
    cudaGetSymbolAddress(&pA1, g_A1);
    cudaGetSymbolAddress(&pA2, g_A2);
    cudaGetSymbolAddress(&pH1, g_H1);
    cudaGetSymbolAddress(&pW1, g_W1);
    cudaGetSymbolAddress(&pW2, g_W2);
    cudaGetSymbolAddress(&pdq1, g_rowdq1);
    cudaGetSymbolAddress(&pdq2, g_rowdq2);
    cudaGetSymbolAddress(&ppart, g_part);
    cudaGetSymbolAddress(&pws1, g_ws1);
    cudaGetSymbolAddress(&pws2, g_ws2);

    // weight quantization (both weights have 4096*1024 elements)
    wabs_partial_kernel<<<1024, 256>>>(w1, (float*)ppart);
    wfinal_kernel<<<1, 1024>>>((float*)ppart, (float*)pws1, (float)W_NUMEL);
    wquant_kernel<<<W_NUMEL / 2048, 256>>>(w1, (float*)pws1, (__nv_bfloat16*)pW1);
    wabs_partial_kernel<<<1024, 256>>>(w2, (float*)ppart);
    wfinal_kernel<<<1, 1024>>>((float*)ppart, (float*)pws2, (float)W_NUMEL);
    wquant_kernel<<<W_NUMEL / 2048, 256>>>(w2, (float*)pws2, (__nv_bfloat16*)pW2);

    // LN1 + act quant
    ln_quant_kernel<1><<<M_ROWS, 256>>>(x, ln1g, ln1b,
                                        (__nv_bfloat16*)pA1, (float*)pdq1);
    // GEMM1 (M x 4096, K=1024) + dequant + bias + GELU
    {
        dim3 grid(H_MID / 128, M_ROWS / 128);
        gemm_bitlinear_kernel<<<grid, 256>>>(
            (const __nv_bfloat16*)pA1, (const __nv_bfloat16*)pW1,
            (const float*)pdq1, (const float*)pws1, b1,
            (float*)pH1, H_MID, D_IN, 1);
    }
    // LN2 + act quant
    ln_quant_kernel<4><<<M_ROWS, 256>>>((const float*)pH1, ln2g, ln2b,
                                        (__nv_bfloat16*)pA2, (float*)pdq2);
    // GEMM2 (M x 1024, K=4096) + dequant + bias
    {
        dim3 grid(D_IN / 128, M_ROWS / 128);
        gemm_bitlinear_kernel<<<grid, 256>>>(
            (const __nv_bfloat16*)pA2, (const __nv_bfloat16*)pW2,
            (const float*)pdq2, (const float*)pws2, b2,
            out, D_IN, H_MID, 0);
    }
}

// round 15
// speedup vs baseline: 1.5584x; 1.5584x over previous
#include <cuda_runtime.h>
#include <cuda_bf16.h>
#include <cstdint>

// Problem dims (fixed by dataset): M = 8*4096 rows, D=1024, H=4096
#define M_ROWS 32768
#define D_IN   1024
#define H_MID  4096
#define W_NUMEL (4096*1024)

// Arch-feature gate: tcgen05 only exists on the "a" variants.
#if defined(__CUDA_ARCH__) && (defined(__CUDA_ARCH_FEAT_SM103_ALL) || defined(__CUDA_ARCH_FEAT_SM100_ALL) || defined(__CUDA_ARCH_FEAT_SM101_ALL))
#define HAS_TCGEN05 1
#else
#define HAS_TCGEN05 0
#endif

// ---------------- scratch (__device__ globals; allocation-free rule) -------
__device__ __align__(1024) __nv_bfloat16 g_A1[(size_t)M_ROWS * D_IN];
__device__ __align__(1024) __nv_bfloat16 g_A2[(size_t)M_ROWS * H_MID];
__device__ __align__(1024) float         g_H1[(size_t)M_ROWS * H_MID];
__device__ __align__(1024) __nv_bfloat16 g_W1[(size_t)W_NUMEL];
__device__ __align__(1024) __nv_bfloat16 g_W2[(size_t)W_NUMEL];
__device__ float g_rowdq1[M_ROWS];
__device__ float g_rowdq2[M_ROWS];
__device__ float g_part[1024];
__device__ float g_ws1[2];   // [quant scale, dequant factor]
__device__ float g_ws2[2];

// ---------------- generic PTX helpers (base-arch safe) ----------------------
__device__ __forceinline__ void cp_async16(uint32_t dst, const void* src) {
    asm volatile("cp.async.cg.shared.global [%0], [%1], 16;\n" :: "r"(dst), "l"(src) : "memory");
}
__device__ __forceinline__ uint32_t sw_off(uint32_t off) {
    return off ^ ((off >> 3) & 0x70);
}
__device__ __forceinline__ uint32_t elect_one_pred() {
    uint32_t pred;
    asm volatile(
        "{\n\t"
        ".reg .pred p;\n\t"
        "elect.sync _|p, 0xFFFFFFFF;\n\t"
        "selp.b32 %0, 1, 0, p;\n\t"
        "}"
        : "=r"(pred));
    return pred;
}

#define MBARRIER_INIT(addr, cnt) \
    asm volatile("mbarrier.init.shared.b64 [%0], %1;" :: "r"((uint32_t)(addr)), "r"((uint32_t)(cnt)) : "memory")

#define MBARRIER_INVAL(addr) \
    asm volatile("mbarrier.inval.shared.b64 [%0];" :: "r"((uint32_t)(addr)) : "memory")

#define MBARRIER_WAIT_PARITY(mbar_smem_addr, phase_parity) do { \
    uint32_t _mbar = (uint32_t)(mbar_smem_addr); \
    uint32_t _parity = (uint32_t)(phase_parity); \
    uint32_t _done; \
    asm volatile( \
        "{\n\t" \
        ".reg .pred p;\n\t" \
        "mbarrier.try_wait.parity.acquire.cta.shared::cta.b64 p, [%1], %2;\n\t" \
        "selp.b32 %0, 1, 0, p;\n\t" \
        "}" \
        : "=r"(_done) : "r"(_mbar), "r"(_parity) : "memory"); \
    if (!_done) { \
        asm volatile( \
            "{\n\t" \
            ".reg .pred P1;\n\t" \
            "WAIT_LOOP_%=:\n\t" \
            "mbarrier.try_wait.parity.acquire.cta.shared::cta.b64 P1, [%0], %1, 0x989680;\n\t" \
            "@P1 bra.uni WAIT_DONE_%=;\n\t" \
            "bra.uni WAIT_LOOP_%=;\n\t" \
            "WAIT_DONE_%=:\n\t" \
            "}" \
            :: "r"(_mbar), "r"(_parity) : "memory"); \
    } \
} while(0)

// ---------------- tcgen05 helpers (only referenced inside HAS_TCGEN05) -----
#define TCGEN05_ALLOC(smem_result_addr, nCols) \
    asm volatile("tcgen05.alloc.cta_group::1.sync.aligned.shared::cta.b32 [%0], %1;" \
        :: "r"((uint32_t)(smem_result_addr)), "r"((uint32_t)(nCols)) : "memory")
#define TCGEN05_DEALLOC(tmem_addr, nCols) \
    asm volatile("tcgen05.dealloc.cta_group::1.sync.aligned.b32 %0, %1;" \
        :: "r"(tmem_addr), "r"((uint32_t)(nCols)))
#define TCGEN05_COMMIT(mbar_smem_addr) \
    asm volatile("tcgen05.commit.cta_group::1.mbarrier::arrive::one.shared::cluster.b64 [%0];" \
        :: "r"((uint32_t)(mbar_smem_addr)) : "memory")
#define TCGEN05_WAIT_LD() \
    asm volatile("tcgen05.wait::ld.sync.aligned;" ::: "memory")
#define TCGEN05_FENCE_AFTER() \
    asm volatile("tcgen05.fence::after_thread_sync;" ::: "memory")
#define TCGEN05_FENCE_BEFORE() \
    asm volatile("tcgen05.fence::before_thread_sync;" ::: "memory")

#define TCGEN05_LD_32X32B_X32(r, tmem_addr) \
    asm volatile( \
        "tcgen05.ld.sync.aligned.32x32b.x32.b32 " \
        "{%0, %1, %2, %3, %4, %5, %6, %7, " \
        " %8, %9, %10, %11, %12, %13, %14, %15, " \
        " %16, %17, %18, %19, %20, %21, %22, %23, " \
        " %24, %25, %26, %27, %28, %29, %30, %31}, [%32];" \
        : "=r"((r)[0]),  "=r"((r)[1]),  "=r"((r)[2]),  "=r"((r)[3]), \
          "=r"((r)[4]),  "=r"((r)[5]),  "=r"((r)[6]),  "=r"((r)[7]), \
          "=r"((r)[8]),  "=r"((r)[9]),  "=r"((r)[10]), "=r"((r)[11]), \
          "=r"((r)[12]), "=r"((r)[13]), "=r"((r)[14]), "=r"((r)[15]), \
          "=r"((r)[16]), "=r"((r)[17]), "=r"((r)[18]), "=r"((r)[19]), \
          "=r"((r)[20]), "=r"((r)[21]), "=r"((r)[22]), "=r"((r)[23]), \
          "=r"((r)[24]), "=r"((r)[25]), "=r"((r)[26]), "=r"((r)[27]), \
          "=r"((r)[28]), "=r"((r)[29]), "=r"((r)[30]), "=r"((r)[31]) \
        : "r"(tmem_addr))

static constexpr uint64_t SMEM_DESC_BASE_SW128 =
    (uint64_t(2)  << 61)    // layout_type = SW128
    | (uint64_t(1) << 46)   // version = 1 (Blackwell)
    | (uint64_t(64) << 32)  // SBO = 64 (1024B per 8-row swizzle block)
    | (uint64_t(1) << 16);  // LBO = 1
#define MAKE_SMEM_DESC(base_addr) \
    (SMEM_DESC_BASE_SW128 | ((uint64_t)((base_addr) >> 4) & 0x3FFF))

#if HAS_TCGEN05
// idesc (kind::f16): dtype=F32(bit4), atype=BF16(bit7), btype=BF16(bit10),
// N=128 -> (128>>3)<<17, M=128 -> (128>>4)<<24   (matches test_mma 0x8080490 scaling)
#define IDESC_M128_N128 ((1u << 4) | (1u << 7) | (1u << 10) | (16u << 17) | (8u << 24))
__device__ __forceinline__ void mma_f16_ss(uint32_t d_tmem, uint64_t a_desc,
                                           uint64_t b_desc, uint32_t acc) {
    asm volatile(
        "{\n\t"
        ".reg .pred p;\n\t"
        "setp.ne.u32 p, %4, 0;\n\t"
        "tcgen05.mma.cta_group::1.kind::f16 [%0], %1, %2, %3, {%5, %5, %5, %5}, p;\n\t"
        "}"
        :: "r"(d_tmem), "l"(a_desc), "l"(b_desc), "r"(IDESC_M128_N128), "r"(acc), "r"(0u)
        : "memory");
}
#endif

// ---------------- small helpers --------------------------------------------
__device__ __forceinline__ float block_sum(float v, float* sb) {
    int tid = threadIdx.x;
    #pragma unroll
    for (int o = 16; o; o >>= 1) v += __shfl_xor_sync(0xffffffffu, v, o);
    __syncthreads();
    if ((tid & 31) == 0) sb[tid >> 5] = v;
    __syncthreads();
    int nw = blockDim.x >> 5;
    float t = (tid < nw) ? sb[tid] : 0.f;
    #pragma unroll
    for (int o = 16; o; o >>= 1) t += __shfl_xor_sync(0xffffffffu, t, o);
    if (tid == 0) sb[0] = t;
    __syncthreads();
    return sb[0];
}

__device__ __forceinline__ float block_max(float v, float* sb) {
    int tid = threadIdx.x;
    #pragma unroll
    for (int o = 16; o; o >>= 1) v = fmaxf(v, __shfl_xor_sync(0xffffffffu, v, o));
    __syncthreads();
    if ((tid & 31) == 0) sb[tid >> 5] = v;
    __syncthreads();
    int nw = blockDim.x >> 5;
    float t = (tid < nw) ? sb[tid] : 0.f;
    #pragma unroll
    for (int o = 16; o; o >>= 1) t = fmaxf(t, __shfl_xor_sync(0xffffffffu, t, o));
    if (tid == 0) sb[0] = t;
    __syncthreads();
    return sb[0];
}

// ---------------- weight quantization (deterministic) -----------------------
__global__ void __launch_bounds__(256) wabs_partial_kernel(
    const float* __restrict__ w, float* __restrict__ part)
{
    __shared__ float sb[64];
    int tid = threadIdx.x;
    const float4* p = (const float4*)w + (size_t)blockIdx.x * 1024;
    float s = 0.f;
    #pragma unroll
    for (int i = 0; i < 4; i++) {
        float4 v = p[tid + 256 * i];
        s += fabsf(v.x) + fabsf(v.y) + fabsf(v.z) + fabsf(v.w);
    }
    s = block_sum(s, sb);
    if (tid == 0) part[blockIdx.x] = s;
}

__global__ void __launch_bounds__(1024) wfinal_kernel(
    const float* __restrict__ part, float* __restrict__ wsout, float n)
{
    __shared__ float sb[64];
    float s = part[threadIdx.x];
    s = block_sum(s, sb);
    if (threadIdx.x == 0) {
        float mean = fmaxf(s / n, 1e-5f);
        wsout[0] = 1.0f / mean;
        wsout[1] = mean;
    }
}

__global__ void __launch_bounds__(256) wquant_kernel(
    const float* __restrict__ w, const float* __restrict__ ws,
    __nv_bfloat16* __restrict__ q)
{
    float s = ws[0];
    size_t base = ((size_t)blockIdx.x * 256 + threadIdx.x) * 8;
    float4 a = *(const float4*)(w + base);
    float4 b = *(const float4*)(w + base + 4);
    __nv_bfloat16 o[8];
    o[0] = __float2bfloat16(fminf(fmaxf(rintf(a.x * s), -1.f), 1.f));
    o[1] = __float2bfloat16(fminf(fmaxf(rintf(a.y * s), -1.f), 1.f));
    o[2] = __float2bfloat16(fminf(fmaxf(rintf(a.z * s), -1.f), 1.f));
    o[3] = __float2bfloat16(fminf(fmaxf(rintf(a.w * s), -1.f), 1.f));
    o[4] = __float2bfloat16(fminf(fmaxf(rintf(b.x * s), -1.f), 1.f));
    o[5] = __float2bfloat16(fminf(fmaxf(rintf(b.y * s), -1.f), 1.f));
    o[6] = __float2bfloat16(fminf(fmaxf(rintf(b.z * s), -1.f), 1.f));
    o[7] = __float2bfloat16(fminf(fmaxf(rintf(b.w * s), -1.f), 1.f));
    *(uint4*)(q + base) = *(uint4*)o;
}

// ---------------- fused LayerNorm + per-row int8 fake-quant -----------------
template <int NV>
__global__ void __launch_bounds__(256) ln_quant_kernel(
    const float* __restrict__ x, const float* __restrict__ g,
    const float* __restrict__ b, __nv_bfloat16* __restrict__ q,
    float* __restrict__ rowdq)
{
    constexpr int L = NV * 1024;
    __shared__ float sb[64];
    int row = blockIdx.x, tid = threadIdx.x;
    const float4* xr = (const float4*)(x + (size_t)row * L);
    float4 v[NV];
    float s = 0.f;
    #pragma unroll
    for (int i = 0; i < NV; i++) {
        v[i] = xr[tid + 256 * i];
        s += v[i].x + v[i].y + v[i].z + v[i].w;
    }
    float mu = block_sum(s, sb) * (1.0f / L);
    float s2 = 0.f;
    #pragma unroll
    for (int i = 0; i < NV; i++) {
        float dx = v[i].x - mu, dy = v[i].y - mu, dz = v[i].z - mu, dw = v[i].w - mu;
        s2 += dx * dx + dy * dy + dz * dz + dw * dw;
    }
    float rstd = rsqrtf(block_sum(s2, sb) * (1.0f / L) + 1e-5f);

    const float4* g4 = (const float4*)g;
    const float4* b4 = (const float4*)b;
    float y[NV * 4];
    float amax = 0.f;
    #pragma unroll
    for (int i = 0; i < NV; i++) {
        float4 gv = g4[tid + 256 * i];
        float4 bv = b4[tid + 256 * i];
        y[i * 4 + 0] = (v[i].x - mu) * rstd * gv.x + bv.x;
        y[i * 4 + 1] = (v[i].y - mu) * rstd * gv.y + bv.y;
        y[i * 4 + 2] = (v[i].z - mu) * rstd * gv.z + bv.z;
        y[i * 4 + 3] = (v[i].w - mu) * rstd * gv.w + bv.w;
        #pragma unroll
        for (int j = 0; j < 4; j++) amax = fmaxf(amax, fabsf(y[i * 4 + j]));
    }
    amax = block_max(amax, sb);
    float scale = 127.f / fmaxf(amax, 1e-5f);
    if (tid == 0) rowdq[row] = 1.0f / scale;

    __nv_bfloat16* qr = q + (size_t)row * L;
    #pragma unroll
    for (int i = 0; i < NV; i++) {
        __nv_bfloat16 o[4];
        #pragma unroll
        for (int j = 0; j < 4; j++) {
            float qv = fminf(fmaxf(rintf(y[i * 4 + j] * scale), -128.f), 127.f);
            o[j] = __float2bfloat16(qv);
        }
        *(uint2*)(qr + (size_t)(tid + 256 * i) * 4) = *(uint2*)o;
    }
}

// ===========================================================================
// PATH A: tcgen05 GEMM 128(M) x 256(N), K staged by 64, double-buffered.
// Single mma-done mbarrier (one completion per K-stage; parity = kt & 1).
// Per iteration kt (stage s = kt&1):
//   1. cp.async.wait_group 0            -> stage s data resident
//   2. fence.proxy.async + syncthreads
//   3. warp0-elect: 8x MMA on stage s, commit(mbar)
//   4. kt>=1: all wait mbar parity (kt-1)&1   -> MMA(kt-1) done (read s^1)
//   5. kt+1<nk: cp.async load stage s^1 <- K-chunk kt+1, commit_group
// ===========================================================================
#define STAGE_BYTES  49152
#define SM_STAGE_OFF 1024
#define GEMM_SMEM    (1024 /*align pad*/ + SM_STAGE_OFF + 2 * STAGE_BYTES)  // 100352

template <int DO_GELU>
__global__ void __launch_bounds__(256) gemm_tc_kernel(
    const __nv_bfloat16* __restrict__ A,
    const __nv_bfloat16* __restrict__ B,
    const float* __restrict__ rowdq,
    const float* __restrict__ ws,
    const float* __restrict__ bias,
    float* __restrict__ out,
    int N, int K)
{
#if HAS_TCGEN05
    extern __shared__ unsigned char smem_raw[];
    uint32_t sraw  = (uint32_t)__cvta_generic_to_shared(smem_raw);
    uint32_t sbase = (sraw + 1023u) & ~1023u;       // 1024B-align for SW128 descriptors
    int tid = threadIdx.x;
    int m0 = blockIdx.y * 128, n0 = blockIdx.x * 256;

    // TMEM alloc: warp 0 only; other warps do nothing (NO relinquish — racing
    // relinquish against the alloc is a trap).
    if ((tid >> 5) == 0) TCGEN05_ALLOC(sbase, 256);
    if (tid == 0) MBARRIER_INIT(sbase + 64, 1);     // mma-done barrier
    __syncthreads();
    uint32_t tmem_base;
    asm volatile("ld.shared.b32 %0, [%1];" : "=r"(tmem_base) : "r"(sbase));

    int nk = K >> 6;  // number of K64 stages

    // stage loader: A rows [m0,m0+128) -> 16KB, B rows [n0,n0+256) as two
    // 128-row SW128 tiles (16KB each). 256 threads x 12 chunks of 16B.
    auto load_stage = [&](int s, int kt) {
        uint32_t aB = sbase + SM_STAGE_OFF + (uint32_t)s * STAGE_BYTES;
        int k0 = kt << 6;
        #pragma unroll
        for (int i = 0; i < 4; i++) {
            int idx = tid + (i << 8);
            int row = idx >> 3, kc = idx & 7;
            cp_async16(aB + sw_off(row * 128 + kc * 16),
                       A + (size_t)(m0 + row) * K + k0 + kc * 8);
        }
        #pragma unroll
        for (int i = 0; i < 4; i++) {
            int idx = tid + (i << 8);
            int row = idx >> 3, kc = idx & 7;
            cp_async16(aB + 16384 + sw_off(row * 128 + kc * 16),
                       B + (size_t)(n0 + row) * K + k0 + kc * 8);
        }
        #pragma unroll
        for (int i = 0; i < 4; i++) {
            int idx = tid + (i << 8);
            int row = idx >> 3, kc = idx & 7;
            cp_async16(aB + 32768 + sw_off(row * 128 + kc * 16),
                       B + (size_t)(n0 + 128 + row) * K + k0 + kc * 8);
        }
        asm volatile("cp.async.commit_group;\n" ::: "memory");
    };

    load_stage(0, 0);

    for (int kt = 0; kt < nk; kt++) {
        int s = kt & 1;
        asm volatile("cp.async.wait_group 0;\n" ::: "memory");
        asm volatile("fence.proxy.async.shared::cta;" ::: "memory");
        __syncthreads();

        if ((tid >> 5) == 0) {
            if (elect_one_pred()) {
                uint32_t aB = sbase + SM_STAGE_OFF + (uint32_t)s * STAGE_BYTES;
                uint64_t adesc  = MAKE_SMEM_DESC(aB);
                uint64_t b0desc = MAKE_SMEM_DESC(aB + 16384);
                uint64_t b1desc = MAKE_SMEM_DESC(aB + 32768);
                #pragma unroll
                for (int j = 0; j < 4; j++) {
                    uint32_t acc = (kt | j) ? 1u : 0u;
                    mma_f16_ss(tmem_base,       adesc + j * 2, b0desc + j * 2, acc);
                    mma_f16_ss(tmem_base + 128, adesc + j * 2, b1desc + j * 2, acc);
                }
                TCGEN05_COMMIT(sbase + 64);
            }
        }

        // Before overwriting buffer s^1 (read by MMA kt-1), wait its completion.
        if (kt >= 1)
            MBARRIER_WAIT_PARITY(sbase + 64, (kt - 1) & 1);
        if (kt + 1 < nk)
            load_stage(s ^ 1, kt + 1);
    }

    // Wait final MMA completion.
    MBARRIER_WAIT_PARITY(sbase + 64, (nk - 1) & 1);
    TCGEN05_FENCE_AFTER();

    // Epilogue: warps 0-3 cols [0,128), warps 4-7 cols [128,256); warp w reads
    // TMEM subpartition w%4 (rows m0 + (w&3)*32 + lane).
    int warp = tid >> 5, lane = tid & 31;
    int sub = warp & 3, half = warp >> 2;
    int row = m0 + sub * 32 + lane;
    float dq = rowdq[row] * ws[1];
    float* orow = out + (size_t)row * N + n0;
    #pragma unroll
    for (int c32 = 0; c32 < 4; c32++) {
        int col0 = half * 128 + c32 * 32;
        uint32_t d[32];
        TCGEN05_LD_32X32B_X32(d, tmem_base + col0);
        TCGEN05_WAIT_LD();
        #pragma unroll
        for (int j = 0; j < 32; j += 4) {
            float4 v;
            v.x = __uint_as_float(d[j + 0]) * dq + bias[n0 + col0 + j + 0];
            v.y = __uint_as_float(d[j + 1]) * dq + bias[n0 + col0 + j + 1];
            v.z = __uint_as_float(d[j + 2]) * dq + bias[n0 + col0 + j + 2];
            v.w = __uint_as_float(d[j + 3]) * dq + bias[n0 + col0 + j + 3];
            if (DO_GELU) {
                v.x = 0.5f * v.x * (1.f + erff(v.x * 0.70710678118654752f));
                v.y = 0.5f * v.y * (1.f + erff(v.y * 0.70710678118654752f));
                v.z = 0.5f * v.z * (1.f + erff(v.z * 0.70710678118654752f));
                v.w = 0.5f * v.w * (1.f + erff(v.w * 0.70710678118654752f));
            }
            *(float4*)(orow + col0 + j) = v;
        }
    }
    TCGEN05_FENCE_BEFORE();
    __syncthreads();
    if (tid == 0) MBARRIER_INVAL(sbase + 64);
    __syncthreads();
    if ((tid >> 5) == 0) TCGEN05_DEALLOC(tmem_base, 256);
#endif  // HAS_TCGEN05
}

// ===========================================================================
// PATH B: mma.sync fallback GEMM (128x128 tile) — active only WITHOUT tcgen05
// (byte-identical math to the R5 kernel that passed at 2135.8us)
// ===========================================================================
__device__ __forceinline__ void mma16816(float* c, const uint32_t* a, const uint32_t* b) {
    asm volatile(
        "mma.sync.aligned.m16n8k16.row.col.f32.bf16.bf16.f32 "
        "{%0,%1,%2,%3}, {%4,%5,%6,%7}, {%8,%9}, {%0,%1,%2,%3};\n"
        : "+f"(c[0]), "+f"(c[1]), "+f"(c[2]), "+f"(c[3])
        : "r"(a[0]), "r"(a[1]), "r"(a[2]), "r"(a[3]), "r"(b[0]), "r"(b[1]));
}
__device__ __forceinline__ void ldsm4(uint32_t* r, uint32_t addr) {
    asm volatile("ldmatrix.sync.aligned.m8n8.x4.shared.b16 {%0,%1,%2,%3}, [%4];\n"
        : "=r"(r[0]), "=r"(r[1]), "=r"(r[2]), "=r"(r[3]) : "r"(addr));
}
__device__ __forceinline__ void ldsm2(uint32_t* r, uint32_t addr) {
    asm volatile("ldmatrix.sync.aligned.m8n8.x2.shared.b16 {%0,%1}, [%2];\n"
        : "=r"(r[0]), "=r"(r[1]) : "r"(addr));
}

#define TILE_B (128 * 40 * 2)

#if !HAS_TCGEN05
__device__ __forceinline__ void load_tiles_fb(
    const __nv_bfloat16* A, const __nv_bfloat16* B,
    uint32_t sA, uint32_t sB, int m0, int n0, int k0, int K, int tid)
{
    #pragma unroll
    for (int i = 0; i < 2; i++) {
        int c = tid + 256 * i;
        int row = c >> 2;
        int kc = (c & 3) * 8;
        cp_async16(sA + row * 80 + kc * 2, A + (size_t)(m0 + row) * K + k0 + kc);
        cp_async16(sB + row * 80 + kc * 2, B + (size_t)(n0 + row) * K + k0 + kc);
    }
}
#endif

template <int DO_GELU>
__global__ void __launch_bounds__(256) gemm_fb_kernel(
    const __nv_bfloat16* __restrict__ A,
    const __nv_bfloat16* __restrict__ B,
    const float* __restrict__ rowdq,
    const float* __restrict__ ws,
    const float* __restrict__ bias,
    float* __restrict__ out,
    int N, int K)
{
#if !HAS_TCGEN05
    __shared__ __align__(16) unsigned char smem[2 * 2 * TILE_B];
    uint32_t sbase = (uint32_t)__cvta_generic_to_shared(smem);
    int tid = threadIdx.x;
    int m0 = blockIdx.y * 128, n0 = blockIdx.x * 128;
    int lane = tid & 31, wid = tid >> 5;
    int wm = (wid >> 2) * 64, wn = (wid & 3) * 32;

    float acc[4][4][4];
    #pragma unroll
    for (int i = 0; i < 4; i++)
        #pragma unroll
        for (int j = 0; j < 4; j++)
            #pragma unroll
            for (int l = 0; l < 4; l++) acc[i][j][l] = 0.f;

    int nk = K >> 5;
    load_tiles_fb(A, B, sbase, sbase + TILE_B, m0, n0, 0, K, tid);
    asm volatile("cp.async.commit_group;\n");
    int buf = 0;
    for (int kt = 0; kt < nk; kt++) {
        asm volatile("cp.async.wait_group 0;\n" ::: "memory");
        __syncthreads();
        if (kt + 1 < nk) {
            uint32_t off = (uint32_t)(buf ^ 1) * (2 * TILE_B);
            load_tiles_fb(A, B, sbase + off, sbase + off + TILE_B, m0, n0, (kt + 1) << 5, K, tid);
            asm volatile("cp.async.commit_group;\n");
        }
        uint32_t aBase = sbase + (uint32_t)buf * (2 * TILE_B);
        uint32_t bBase = aBase + TILE_B;
        #pragma unroll
        for (int kk = 0; kk < 2; kk++) {
            uint32_t a[4][4], b[4][2];
            #pragma unroll
            for (int mi = 0; mi < 4; mi++) {
                uint32_t addr = aBase + (uint32_t)(wm + mi * 16 + (lane & 15)) * 80
                              + (uint32_t)(kk * 16 + (lane >> 4) * 8) * 2;
                ldsm4(a[mi], addr);
            }
            #pragma unroll
            for (int ni = 0; ni < 4; ni++) {
                int l = lane & 15;
                uint32_t addr = bBase + (uint32_t)(wn + ni * 8 + (l & 7)) * 80
                              + (uint32_t)(kk * 16 + (l >> 3) * 8) * 2;
                ldsm2(b[ni], addr);
            }
            #pragma unroll
            for (int mi = 0; mi < 4; mi++)
                #pragma unroll
                for (int ni = 0; ni < 4; ni++)
                    mma16816(acc[mi][ni], a[mi], b[ni]);
        }
        buf ^= 1;
    }

    float wv = ws[1];
    #pragma unroll
    for (int mi = 0; mi < 4; mi++) {
        int r0 = m0 + wm + mi * 16 + (lane >> 2);
        float dq0 = rowdq[r0] * wv;
        float dq1 = rowdq[r0 + 8] * wv;
        #pragma unroll
        for (int ni = 0; ni < 4; ni++) {
            int col = n0 + wn + ni * 8 + (lane & 3) * 2;
            float bs0 = bias[col], bs1 = bias[col + 1];
            float v0 = acc[mi][ni][0] * dq0 + bs0;
            float v1 = acc[mi][ni][1] * dq0 + bs1;
            float v2 = acc[mi][ni][2] * dq1 + bs0;
            float v3 = acc[mi][ni][3] * dq1 + bs1;
            if (DO_GELU) {
                v0 = 0.5f * v0 * (1.f + erff(v0 * 0.70710678118654752f));
                v1 = 0.5f * v1 * (1.f + erff(v1 * 0.70710678118654752f));
                v2 = 0.5f * v2 * (1.f + erff(v2 * 0.70710678118654752f));
                v3 = 0.5f * v3 * (1.f + erff(v3 * 0.70710678118654752f));
            }
            *(float2*)&out[(size_t)r0 * N + col]       = make_float2(v0, v1);
            *(float2*)&out[(size_t)(r0 + 8) * N + col] = make_float2(v2, v3);
        }
    }
#endif  // !HAS_TCGEN05
}

// ---------------- launch ----------------------------------------------------
extern "C" void kernel_launch(void* const* d_in, const int* in_sizes, int n_in,
                              void* d_out, int out_size)
{
    const float* x    = (const float*)d_in[0];
    const float* ln1g = (const float*)d_in[1];
    const float* ln1b = (const float*)d_in[2];
    const float* w1   = (const float*)d_in[3];
    const float* b1   = (const float*)d_in[4];
    const float* ln2g = (const float*)d_in[5];
    const float* ln2b = (const float*)d_in[6];
    const float* w2   = (const float*)d_in[7];
    const float* b2   = (const float*)d_in[8];
    float* out = (float*)d_out;

    void *pA1, *pA2, *pH1, *pW1, *pW2, *pdq1, *pdq2, *ppart, *pws1, *pws2;
    cudaGetSymbolAddress(&pA1, g_A1);
    cudaGetSymbolAddress(&pA2, g_A2);
    cudaGetSymbolAddress(&pH1, g_H1);
    cudaGetSymbolAddress(&pW1, g_W1);
    cudaGetSymbolAddress(&pW2, g_W2);
    cudaGetSymbolAddress(&pdq1, g_rowdq1);
    cudaGetSymbolAddress(&pdq2, g_rowdq2);
    cudaGetSymbolAddress(&ppart, g_part);
    cudaGetSymbolAddress(&pws1, g_ws1);
    cudaGetSymbolAddress(&pws2, g_ws2);

    cudaFuncSetAttribute(gemm_tc_kernel<1>,
                         cudaFuncAttributeMaxDynamicSharedMemorySize, GEMM_SMEM);
    cudaFuncSetAttribute(gemm_tc_kernel<0>,
                         cudaFuncAttributeMaxDynamicSharedMemorySize, GEMM_SMEM);

    // weight quantization
    wabs_partial_kernel<<<1024, 256>>>(w1, (float*)ppart);
    wfinal_kernel<<<1, 1024>>>((float*)ppart, (float*)pws1, (float)W_NUMEL);
    wquant_kernel<<<W_NUMEL / 2048, 256>>>(w1, (float*)pws1, (__nv_bfloat16*)pW1);
    wabs_partial_kernel<<<1024, 256>>>(w2, (float*)ppart);
    wfinal_kernel<<<1, 1024>>>((float*)ppart, (float*)pws2, (float)W_NUMEL);
    wquant_kernel<<<W_NUMEL / 2048, 256>>>(w2, (float*)pws2, (__nv_bfloat16*)pW2);

    // LN1 + act quant
    ln_quant_kernel<1><<<M_ROWS, 256>>>(x, ln1g, ln1b,
                                        (__nv_bfloat16*)pA1, (float*)pdq1);
    // GEMM1 (M x 4096, K=1024) + dequant + bias + GELU — both paths enqueued;
    // exactly one has a live body on the SASS the driver selects.
    {
        dim3 grid_tc(H_MID / 256, M_ROWS / 128);
        gemm_tc_kernel<1><<<grid_tc, 256, GEMM_SMEM>>>(
            (const __nv_bfloat16*)pA1, (const __nv_bfloat16*)pW1,
            (const float*)pdq1, (const float*)pws1, b1,
            (float*)pH1, H_MID, D_IN);
        dim3 grid_fb(H_MID / 128, M_ROWS / 128);
        gemm_fb_kernel<1><<<grid_fb, 256>>>(
            (const __nv_bfloat16*)pA1, (const __nv_bfloat16*)pW1,
            (const float*)pdq1, (const float*)pws1, b1,
            (float*)pH1, H_MID, D_IN);
    }
    // LN2 + act quant
    ln_quant_kernel<4><<<M_ROWS, 256>>>((const float*)pH1, ln2g, ln2b,
                                        (__nv_bfloat16*)pA2, (float*)pdq2);
    // GEMM2 (M x 1024, K=4096) + dequant + bias
    {
        dim3 grid_tc(D_IN / 256, M_ROWS / 128);
        gemm_tc_kernel<0><<<grid_tc, 256, GEMM_SMEM>>>(
            (const __nv_bfloat16*)pA2, (const __nv_bfloat16*)pW2,
            (const float*)pdq2, (const float*)pws2, b2,
            out, D_IN, H_MID);
        dim3 grid_fb(D_IN / 128, M_ROWS / 128);
        gemm_fb_kernel<0><<<grid_fb, 256>>>(
            (const __nv_bfloat16*)pA2, (const __nv_bfloat16*)pW2,
            (const float*)pdq2, (const float*)pws2, b2,
            out, D_IN, H_MID);
    }
}